// round 13
// baseline (speedup 1.0000x reference)
#include <cuda_runtime.h>
#include <cuda_bf16.h>
#include <cstdint>

// ============================================================================
// out = patches @ (w_patch @ [w_reg|w_obj]) + bias, anchor decode.
//   kD : dummy (ncu ordinal shim)
//   kA1: W2 partials (grid 24x8, block 384, d-chunks of 96)
//   kA2: reduce 8 partials -> g_Bfrag (bf16, px-permuted HMMA frag order)
//   kB : HMMA GEMM. B staged ONCE into CTA smem (LDS path — decoupled from
//        the per-SM LDG completion FIFO); A = pure streaming LDG (__ldcs,
//        2-step reg prefetch). K-split x4, M-split x2, grid 1024 x 256.
// ============================================================================

__device__ float g_part[8 * 12 * 768 * 4];               // [p][jq][pc][4]
__device__ __align__(16) unsigned int g_Bfrag[48 * 6 * 32 * 2];

__device__ __forceinline__ uint32_t smem_u32(const void* p) {
    uint32_t a;
    asm("{ .reg .u64 t; cvta.to.shared.u64 t, %1; cvt.u32.u64 %0, t; }"
        : "=r"(a) : "l"(p));
    return a;
}

// ---------------------------------------------------------------------------
__global__ void kD() { if (threadIdx.x == 0) g_part[0] = 0.f; }

// ---------------------------------------------------------------------------
// kA1: grid (24, 8), block 384. CTA = 32 pc-rows x 96 d x 48 j.
// ---------------------------------------------------------------------------
__global__ void __launch_bounds__(384) kA1(const float* __restrict__ w_patch,
                                           const float* __restrict__ w_reg,
                                           const float* __restrict__ w_obj)
{
    __shared__ __align__(16) float sWc[96 * 48];
    __shared__ float sWp[32 * 97];

    const int tid = threadIdx.x;
    const int r0  = blockIdx.x * 32;
    const int d0  = blockIdx.y * 96;

    #pragma unroll
    for (int i = tid; i < 96 * 48; i += 384) {
        int d = i / 48, j = i % 48;
        float v = 0.f;
        if (j < 36)       v = w_reg[(size_t)(d0 + d) * 36 + j];
        else if (j < 45)  v = w_obj[(size_t)(d0 + d) * 9 + (j - 36)];
        sWc[i] = v;
    }
    #pragma unroll
    for (int i = tid; i < 32 * 96; i += 384) {
        int r = i / 96, d = i % 96;
        sWp[r * 97 + d] = w_patch[(size_t)(r0 + r) * 768 + d0 + d];
    }
    __syncthreads();

    const int jq = tid >> 5;          // warp-uniform -> broadcast LDS
    const int rl = tid & 31;
    float4 acc = make_float4(0.f, 0.f, 0.f, 0.f);
    #pragma unroll 8
    for (int dd = 0; dd < 96; ++dd) {
        float4 w = *(const float4*)&sWc[dd * 48 + jq * 4];
        float  a = sWp[rl * 97 + dd];
        acc.x += a * w.x; acc.y += a * w.y; acc.z += a * w.z; acc.w += a * w.w;
    }
    ((float4*)g_part)[((size_t)blockIdx.y * 12 + jq) * 768 + r0 + rl] = acc;
}

// ---------------------------------------------------------------------------
// kA2: reduce 8 partials; bf16 frags, px-permuted k mapping:
//   px = pc&15, q = px&3, t4p = px>>2, k = (q<2) ? 2*t4p+q : 8+2*t4p+(q-2)
// ---------------------------------------------------------------------------
__global__ void kA2()
{
    int t = blockIdx.x * 256 + threadIdx.x;
    if (t >= 9216) return;
    const int jq = t / 768, pc = t % 768;
    const float4* p = (const float4*)g_part;
    float4 s = make_float4(0.f, 0.f, 0.f, 0.f);
    #pragma unroll
    for (int k = 0; k < 8; ++k) {
        float4 v = p[((size_t)k * 12 + jq) * 768 + pc];
        s.x += v.x; s.y += v.y; s.z += v.z; s.w += v.w;
    }
    float sv[4] = {s.x, s.y, s.z, s.w};
    const int st = pc >> 4, px = pc & 15;
    const int q = px & 3, t4p = px >> 2;
    const int k = (q < 2) ? (2 * t4p + q) : (8 + 2 * t4p + (q - 2));
    unsigned short* dst = (unsigned short*)g_Bfrag;
    #pragma unroll
    for (int c = 0; c < 4; ++c) {
        int j = jq * 4 + c;
        int tf = j >> 3;
        int lane = ((j & 7) << 2) | ((k >> 1) & 3);
        __nv_bfloat16 v = __float2bfloat16_rn(sv[c]);
        dst[(((st * 6 + tf) * 32 + lane) * 2 + (k >> 3)) * 2 + (k & 1)] =
            *(unsigned short*)&v;
    }
}

// ---------------------------------------------------------------------------
// kB: grid 1024 (b*32 + fy), block 256 = 8 warps. CTA = 32 cells (fy row).
// Warp w: ks = w>>1 (12 K-steps), mh = w&1 (cells mh*16..mh*16+15).
// B: full 72KB fragment image staged to smem once; mainloop reads via LDS
//    (separate fixed-latency path — NOT behind the LDG completion FIFO).
// A: __ldcs 2xLDG.128 per step, 2-step register prefetch (only LDG traffic).
// ---------------------------------------------------------------------------
#define SB_OFF    0              // 73728 B; reused for sPart after mainloop
#define BIAS_OFF  73728
#define TK_OFF    73920
#define TQ_OFF    73984
#define TBW_OFF   74048
#define TBH_OFF   74096
#define SMEMB     74240

__global__ void __launch_bounds__(256, 3) kB(
    const float* __restrict__ img,
    const float* __restrict__ b_reg,
    const float* __restrict__ b_obj,
    float* __restrict__ out)
{
    extern __shared__ __align__(16) char sm[];
    const uint32_t smem = smem_u32(sm);
    const int tid  = threadIdx.x;
    const int wid  = tid >> 5;
    const int lane = tid & 31;
    const int fy   = blockIdx.x & 31;
    const int b    = blockIdx.x >> 5;

    // ---- stage full B fragment image (73728 B) into smem, coalesced ----
    {
        const float4* src = (const float4*)g_Bfrag;
        float4*       dst = (float4*)(sm + SB_OFF);
        #pragma unroll
        for (int i = 0; i < 18; ++i)
            dst[tid + 256 * i] = src[tid + 256 * i];
    }
    if (tid < 48) ((float*)(sm + BIAS_OFF))[tid] =
        (tid < 36) ? b_reg[tid] : ((tid < 45) ? b_obj[tid - 36] : 0.f);
    if (tid < 63) {
        ((unsigned char*)(sm + TK_OFF))[tid] = (unsigned char)(tid / 7);
        ((unsigned char*)(sm + TQ_OFF))[tid] = (unsigned char)(tid % 7);
    }
    if (tid < 9) {
        ((float*)(sm + TBW_OFF))[tid] = (float)(2 << (tid % 3));
        ((float*)(sm + TBH_OFF))[tid] = (float)(2 << (tid / 3));
    }
    __syncthreads();

    const int ks = wid >> 1;             // K quarter: steps ks*12..+11
    const int mh = wid & 1;              // M half: cells mh*16..+15
    const int g  = lane >> 2;
    const int t4 = lane & 3;
    const int s0 = ks * 12;

    // lane A base: cell mh*16+g, px 4*t4 (px-permuted frag = contiguous f4)
    const float* base = img + ((size_t)(b * 3) * 512 + (size_t)fy * 16) * 512
                      + (mh * 16 + g) * 16 + 4 * t4;
    // lane B base (smem): + s*1536 + t*256 selects (step, tile)
    const uint32_t sBl = smem + SB_OFF + lane * 8;

    #define SOFF(s) ((size_t)((((s) >> 4) << 9) + ((s) & 15)) << 9)

    float d[6][4];
    #pragma unroll
    for (int t = 0; t < 6; ++t)
        #pragma unroll
        for (int q = 0; q < 4; ++q) d[t][q] = 0.f;

    #define LOADA(f0_, f1_, s) do {                  \
        const float* p_ = base + SOFF(s);            \
        f0_ = __ldcs((const float4*)(p_));           \
        f1_ = __ldcs((const float4*)(p_ + 128));     \
    } while (0)

    #define COMPUTE(f0_, f1_, s) do {                                         \
        uint32_t a0_, a1_, a2_, a3_;                                          \
        { __nv_bfloat162 h_ = __float22bfloat162_rn(make_float2(f0_.x, f0_.y)); a0_ = *(uint32_t*)&h_; } \
        { __nv_bfloat162 h_ = __float22bfloat162_rn(make_float2(f1_.x, f1_.y)); a1_ = *(uint32_t*)&h_; } \
        { __nv_bfloat162 h_ = __float22bfloat162_rn(make_float2(f0_.z, f0_.w)); a2_ = *(uint32_t*)&h_; } \
        { __nv_bfloat162 h_ = __float22bfloat162_rn(make_float2(f1_.z, f1_.w)); a3_ = *(uint32_t*)&h_; } \
        uint2 Bv_[6];                                                         \
        _Pragma("unroll")                                                     \
        for (int t_ = 0; t_ < 6; ++t_)                                        \
            asm volatile("ld.shared.v2.u32 {%0,%1}, [%2];"                    \
                : "=r"(Bv_[t_].x), "=r"(Bv_[t_].y)                            \
                : "r"(sBl + (s) * 1536 + t_ * 256));                          \
        _Pragma("unroll")                                                     \
        for (int t_ = 0; t_ < 6; ++t_)                                        \
            asm volatile(                                                     \
                "mma.sync.aligned.m16n8k16.row.col.f32.bf16.bf16.f32 "        \
                "{%0,%1,%2,%3}, {%4,%5,%6,%7}, {%8,%9}, {%0,%1,%2,%3};"       \
                : "+f"(d[t_][0]), "+f"(d[t_][1]), "+f"(d[t_][2]), "+f"(d[t_][3]) \
                : "r"(a0_), "r"(a1_), "r"(a2_), "r"(a3_),                     \
                  "r"(Bv_[t_].x), "r"(Bv_[t_].y));                            \
    } while (0)

    float4 A0a, A0b, A1a, A1b;
    LOADA(A0a, A0b, s0);
    LOADA(A1a, A1b, s0 + 1);

    #pragma unroll
    for (int i = 0; i < 6; ++i) {
        const int s  = s0 + 2 * i;
        const int n0 = (2 * i + 2 < 12) ? s + 2 : s0 + 11;
        const int n1 = (2 * i + 3 < 12) ? s + 3 : s0 + 11;
        COMPUTE(A0a, A0b, s);
        LOADA(A0a, A0b, n0);
        COMPUTE(A1a, A1b, s + 1);
        LOADA(A1a, A1b, n1);
    }

    // ---- all warps done reading B smem before reuse as sPart ----
    __syncthreads();

    // ---- epilogue: partials to sPart[ks][32][49] ----
    float* sPart = (float*)(sm + SB_OFF);
    float* sBias = (float*)(sm + BIAS_OFF);
    #pragma unroll
    for (int cc = 0; cc < 2; ++cc) {
        const int cell = mh * 16 + cc * 8 + g;
        float* dst = sPart + (ks * 32 + cell) * 49;
        #pragma unroll
        for (int t = 0; t < 6; ++t) {
            const int j = t * 8 + t4 * 2;
            dst[j]     = d[t][2 * cc];
            dst[j + 1] = d[t][2 * cc + 1];
        }
    }
    __syncthreads();

    // ---- reduce 4 ks partials (+bias) into sPart[0] ----
    #pragma unroll
    for (int i = 0; i < 7; ++i) {
        int idx = tid + 256 * i;
        if (idx < 32 * 49) {
            int j = idx % 49;
            if (j < 48) {
                sPart[idx] = sPart[idx] + sPart[idx + 32 * 49]
                           + sPart[idx + 2 * 32 * 49] + sPart[idx + 3 * 32 * 49]
                           + sBias[j];
            }
        }
    }
    __syncthreads();

    // ---- decode + coalesced store: 32 cells * 63 = 2016 floats ----
    const unsigned char* tK = (const unsigned char*)(sm + TK_OFF);
    const unsigned char* tQ = (const unsigned char*)(sm + TQ_OFF);
    const float* tBW = (const float*)(sm + TBW_OFF);
    const float* tBH = (const float*)(sm + TBH_OFF);
    float* obase = out + (size_t)blockIdx.x * 2016;
    const float bb_f = (float)b;
    const float fy_f = (float)fy * 16.f;

    int cell = tid / 63;
    int r    = tid - cell * 63;
    int idx  = tid;
    #pragma unroll
    for (int i = 0; i < 8; ++i) {
        if (idx < 2016) {
            const int k = tK[r], q = tQ[r];
            const float* v = sPart + cell * 49;
            float res;
            if (q == 0)      res = (float)cell * 16.f + v[4 * k];
            else if (q == 1) res = fy_f + v[4 * k + 1];
            else if (q == 2) res = (float)cell * 16.f + v[4 * k] + tBW[k] * v[4 * k + 2];
            else if (q == 3) res = fy_f + v[4 * k + 1] + tBH[k] * v[4 * k + 3];
            else if (q == 4) res = bb_f;
            else if (q == 5) res = 1.f / (1.f + __expf(-v[36 + k]));
            else             res = (float)k;
            obase[idx] = res;
        }
        idx += 256; r += 4; cell += 4;
        if (r >= 63) { r -= 63; cell++; }
    }
}

// ---------------------------------------------------------------------------
extern "C" void kernel_launch(void* const* d_in, const int* in_sizes, int n_in,
                              void* d_out, int out_size)
{
    const float* img     = (const float*)d_in[0];
    const float* w_patch = (const float*)d_in[1];
    const float* w_reg   = (const float*)d_in[2];
    const float* b_reg   = (const float*)d_in[3];
    const float* w_obj   = (const float*)d_in[4];
    const float* b_obj   = (const float*)d_in[5];
    float* out = (float*)d_out;

    kD<<<1, 32>>>();                              // ordinal shim for ncu
    kA1<<<dim3(24, 8), 384>>>(w_patch, w_reg, w_obj);
    kA2<<<36, 256>>>();

    cudaFuncSetAttribute(kB, cudaFuncAttributeMaxDynamicSharedMemorySize, SMEMB);
    kB<<<1024, 256, SMEMB>>>(img, b_reg, b_obj, out);
}